// round 2
// baseline (speedup 1.0000x reference)
#include <cuda_runtime.h>
#include <cuda_bf16.h>
#include <cstdint>
#include <cstddef>

#define T_LEN 4096
#define EMBD  300
#define HID   512
#define KTAG  20
#define START_TAG 18
#define STOP_TAG  19
#define NEGV  (-10000.0f)

// ---------------- scratch (static device globals; no allocation) ----------------
__device__ float    g_xproj[2][T_LEN][4 * HID];   // 64 MB: input projections (bias included)
__device__ float    g_hs[2][T_LEN][HID];          // 16 MB: LSTM outputs (scan order per dir)
__device__ float    g_feats[T_LEN][KTAG];
__device__ float    g_h[2][2][HID];               // [dir][parity][H] double-buffered h
__device__ unsigned g_ctr[2];                     // per-direction step barrier counters

// ---------------- init: reset counters, seed h0 ----------------
__global__ void init_kernel(const float* __restrict__ h0) {
    int tid = threadIdx.x;
    if (tid < 2) g_ctr[tid] = 0u;
    for (int i = tid; i < 2 * HID; i += blockDim.x) {
        g_h[i / HID][0][i % HID] = h0[i];
    }
}

// ---------------- K1: x_proj = emb(gather) @ w_ih^T + b_ih + b_hh ----------------
// Tiled fp32 GEMM: BM=64 (t), BN=64 (j), BK=8, 256 threads, 4x4 microtile.
__global__ __launch_bounds__(256) void xproj_kernel(
    const int*   __restrict__ sentence,
    const float* __restrict__ embed,
    const float* __restrict__ w_ih_f, const float* __restrict__ b_ih_f, const float* __restrict__ b_hh_f,
    const float* __restrict__ w_ih_b, const float* __restrict__ b_ih_b, const float* __restrict__ b_hh_b)
{
    const int dir = blockIdx.z;
    const float* __restrict__ w_ih = dir ? w_ih_b : w_ih_f;
    const float* __restrict__ bi   = dir ? b_ih_b : b_ih_f;
    const float* __restrict__ bh   = dir ? b_hh_b : b_hh_f;

    const int j0 = blockIdx.x * 64;
    const int t0 = blockIdx.y * 64;

    __shared__ __align__(16) float As[8][64];
    __shared__ __align__(16) float Bs[8][64];
    __shared__ int sidx[64];

    const int tid = threadIdx.x;
    if (tid < 64) {
        int t = t0 + tid;
        sidx[tid] = sentence[dir ? (T_LEN - 1 - t) : t];
    }
    __syncthreads();

    const int tx = tid & 15, ty = tid >> 4;
    const int lr = tid >> 2;          // 0..63
    const int le = (tid & 3) * 2;     // 0,2,4,6

    float acc[4][4] = {};

    for (int e0 = 0; e0 < EMBD; e0 += 8) {
        const float* arow = embed + (size_t)sidx[lr] * EMBD;
        const float* brow = w_ih + (size_t)(j0 + lr) * EMBD;
        int e = e0 + le;
        As[le][lr]     = (e     < EMBD) ? arow[e]     : 0.f;
        As[le + 1][lr] = (e + 1 < EMBD) ? arow[e + 1] : 0.f;
        Bs[le][lr]     = (e     < EMBD) ? brow[e]     : 0.f;
        Bs[le + 1][lr] = (e + 1 < EMBD) ? brow[e + 1] : 0.f;
        __syncthreads();
#pragma unroll
        for (int kk = 0; kk < 8; kk++) {
            float4 a = *(const float4*)&As[kk][ty * 4];
            float4 b = *(const float4*)&Bs[kk][tx * 4];
            float av[4] = {a.x, a.y, a.z, a.w};
            float bv[4] = {b.x, b.y, b.z, b.w};
#pragma unroll
            for (int i = 0; i < 4; i++)
#pragma unroll
                for (int j = 0; j < 4; j++)
                    acc[i][j] = fmaf(av[i], bv[j], acc[i][j]);
        }
        __syncthreads();
    }

#pragma unroll
    for (int i = 0; i < 4; i++) {
        int t = t0 + ty * 4 + i;
#pragma unroll
        for (int j = 0; j < 4; j++) {
            int jj = j0 + tx * 4 + j;
            g_xproj[dir][t][jj] = acc[i][j] + bi[jj] + bh[jj];
        }
    }
}

// ---------------- K3: persistent BiLSTM recurrence ----------------
// 128 CTAs: CTA (dir, cid) owns h-indices [8*cid, 8*cid+8) -> 32 gate rows.
// Weights register-resident (64 fp32/thread). h broadcast via double-buffered
// global vector + per-direction release/acquire counter barrier.
__global__ __launch_bounds__(256) void lstm_kernel(
    const float* __restrict__ w_hh_f,
    const float* __restrict__ w_hh_b,
    const float* __restrict__ c0)
{
    const int dir = blockIdx.x >> 6;
    const int cid = blockIdx.x & 63;
    const float* __restrict__ w_hh = dir ? w_hh_b : w_hh_f;

    const int tid  = threadIdx.x;
    const int wid  = tid >> 5;
    const int lane = tid & 31;
    const int gate = lane >> 3;       // 0:i 1:f 2:g 3:o
    const int hloc = lane & 7;
    const int hidx = cid * 8 + hloc;
    const int grow = gate * HID + hidx;

    // load weight slice into registers: w_hh[grow, wid*64 .. wid*64+63]
    float w[64];
    {
        const float* wr = w_hh + (size_t)grow * HID + wid * 64;
#pragma unroll
        for (int k = 0; k < 64; k++) w[k] = wr[k];
    }

    __shared__ __align__(16) float h_sh[HID];
    __shared__ float part[8][32];

    float creg = 0.f, xp = 0.f;
    if (wid == 0) {
        if (lane < 8) creg = c0[dir * HID + hidx];
        xp = g_xproj[dir][0][grow];
    }

    unsigned* ctr = &g_ctr[dir];

    for (int t = 0; t < T_LEN; t++) {
        if (t > 0) {
            if (tid == 0) {
                unsigned target = (unsigned)t * 64u;
                unsigned v;
                do {
                    asm volatile("ld.acquire.gpu.global.u32 %0, [%1];"
                                 : "=r"(v) : "l"(ctr) : "memory");
                } while (v < target);
            }
            __syncthreads();
        }
        // broadcast current h (parity t&1) into shared
        {
            const float2* hgp = (const float2*)g_h[dir][t & 1];
            float2 hv = __ldcg(hgp + tid);
            h_sh[2 * tid]     = hv.x;
            h_sh[2 * tid + 1] = hv.y;
        }
        __syncthreads();

        // 64-wide partial dot: row grow, k-chunk [wid*64, wid*64+64)
        float a0 = 0.f, a1 = 0.f, a2 = 0.f, a3 = 0.f;
#pragma unroll
        for (int kk = 0; kk < 16; kk++) {
            float4 h4 = *(const float4*)&h_sh[wid * 64 + kk * 4];
            a0 = fmaf(w[kk * 4 + 0], h4.x, a0);
            a1 = fmaf(w[kk * 4 + 1], h4.y, a1);
            a2 = fmaf(w[kk * 4 + 2], h4.z, a2);
            a3 = fmaf(w[kk * 4 + 3], h4.w, a3);
        }
        part[wid][lane] = (a0 + a1) + (a2 + a3);
        __syncthreads();

        if (wid == 0) {
            float s = xp;
#pragma unroll
            for (int q = 0; q < 8; q++) s += part[q][lane];
            // gather the 4 gate preactivations for h-index hloc
            float vi = __shfl_sync(0xffffffffu, s, hloc);
            float vf = __shfl_sync(0xffffffffu, s, 8 + hloc);
            float vg = __shfl_sync(0xffffffffu, s, 16 + hloc);
            float vo = __shfl_sync(0xffffffffu, s, 24 + hloc);
            if (lane < 8) {
                float fi = 1.f / (1.f + expf(-vi));
                float ff = 1.f / (1.f + expf(-vf));
                float fo = 1.f / (1.f + expf(-vo));
                creg = ff * creg + fi * tanhf(vg);
                float hn = fo * tanhf(creg);
                g_h[dir][(t + 1) & 1][hidx] = hn;   // write NEXT parity buffer
                g_hs[dir][t][hidx] = hn;
            }
            if (t + 1 < T_LEN) xp = g_xproj[dir][t + 1][grow];  // prefetch
            __threadfence();
            __syncwarp();
            if (lane == 0) atomicAdd(ctr, 1u);
        }
    }
}

// ---------------- K4: feats[t,k] = [h_f(t), h_b(t)] . W_tag[k] + b_tag[k] ----------------
__global__ __launch_bounds__(256) void feats_kernel(
    const float* __restrict__ W_tag, const float* __restrict__ b_tag)
{
    const int t = blockIdx.x;
    __shared__ float hsm[2 * HID];
    const int tid = threadIdx.x;
    for (int i = tid; i < HID; i += 256) {
        hsm[i]       = g_hs[0][t][i];
        hsm[HID + i] = g_hs[1][T_LEN - 1 - t][i];   // bwd dir stored in scan order
    }
    __syncthreads();
    const int wid = tid >> 5, lane = tid & 31;
    for (int k = wid; k < KTAG; k += 8) {
        const float* wrow = W_tag + (size_t)k * (2 * HID);
        float s = 0.f;
#pragma unroll
        for (int m = 0; m < 32; m++)
            s = fmaf(wrow[m * 32 + lane], hsm[m * 32 + lane], s);
#pragma unroll
        for (int off = 16; off; off >>= 1)
            s += __shfl_xor_sync(0xffffffffu, s, off);
        if (lane == 0) g_feats[t][k] = s + b_tag[k];
    }
}

// ---------------- K5: CRF forward scan + gold score ----------------
// LSE_i(a_i + T_ji) = M + log( sum_i exp(T_ji) * exp(a_i - M) ),  E = exp(T) precomputed.
__global__ void crf_kernel(const int* __restrict__ tags,
                           const float* __restrict__ trans,
                           float* __restrict__ out)
{
    __shared__ float Esh[KTAG][KTAG + 1];
    __shared__ float partial[128];
    __shared__ float s_tstop[KTAG];
    const int tid = threadIdx.x;

    // FIX (R1 NaN): fill ALL 400 entries of Esh with a strided loop
    // (previous code used `if (tid < 400)` with only 128 threads ->
    //  rows 6..19 were uninitialized shared memory -> NaN).
    for (int i = tid; i < KTAG * KTAG; i += blockDim.x)
        Esh[i / KTAG][i % KTAG] = __expf(trans[i]);
    if (tid < KTAG) s_tstop[tid] = trans[STOP_TAG * KTAG + tid];
    __syncthreads();

    // gold path score (deterministic reduction)
    float loc = 0.f;
    for (int t = tid; t < T_LEN; t += 128) {
        int tg = tags[t];
        int pv = t ? tags[t - 1] : START_TAG;
        loc += trans[tg * KTAG + pv] + g_feats[t][tg];
    }
    partial[tid] = loc;
    __syncthreads();
    if (tid == 0) {
        float gd = trans[STOP_TAG * KTAG + tags[T_LEN - 1]];
        for (int i = 0; i < 128; i++) gd += partial[i];
        partial[0] = gd;
    }
    __syncthreads();

    if (tid < 32) {
        const int lane = tid;
        float al = (lane == START_TAG) ? 0.f : ((lane < KTAG) ? NEGV : -INFINITY);
        const float* erow = Esh[(lane < KTAG) ? lane : 0];
        float fcur = (lane < KTAG) ? g_feats[0][lane] : 0.f;

        for (int t = 0; t < T_LEN; t++) {
            float fnxt = ((t + 1 < T_LEN) && lane < KTAG) ? g_feats[t + 1][lane] : 0.f;
            float m = al;
#pragma unroll
            for (int off = 16; off; off >>= 1)
                m = fmaxf(m, __shfl_xor_sync(0xffffffffu, m, off));
            float e = __expf(al - m);
            float s0 = 0.f, s1 = 0.f, s2 = 0.f, s3 = 0.f;
#pragma unroll
            for (int i = 0; i < KTAG; i += 4) {
                s0 = fmaf(erow[i],     __shfl_sync(0xffffffffu, e, i),     s0);
                s1 = fmaf(erow[i + 1], __shfl_sync(0xffffffffu, e, i + 1), s1);
                s2 = fmaf(erow[i + 2], __shfl_sync(0xffffffffu, e, i + 2), s2);
                s3 = fmaf(erow[i + 3], __shfl_sync(0xffffffffu, e, i + 3), s3);
            }
            float an = m + __logf((s0 + s1) + (s2 + s3)) + fcur;
            al = (lane < KTAG) ? an : -INFINITY;
            fcur = fnxt;
        }
        // forward_score = LSE_i( alpha_i + T[STOP, i] )
        float v = (lane < KTAG) ? (al + s_tstop[lane]) : -INFINITY;
        float m2 = v;
#pragma unroll
        for (int off = 16; off; off >>= 1)
            m2 = fmaxf(m2, __shfl_xor_sync(0xffffffffu, m2, off));
        float se = __expf(v - m2);
#pragma unroll
        for (int off = 16; off; off >>= 1)
            se += __shfl_xor_sync(0xffffffffu, se, off);
        if (lane == 0) out[0] = (m2 + __logf(se)) - partial[0];
    }
}

// ---------------- launch ----------------
extern "C" void kernel_launch(void* const* d_in, const int* in_sizes, int n_in,
                              void* d_out, int out_size)
{
    const int*   sentence = (const int*)d_in[0];
    const int*   tags     = (const int*)d_in[1];
    const float* embed    = (const float*)d_in[2];
    const float* w_ih_f   = (const float*)d_in[3];
    const float* w_hh_f   = (const float*)d_in[4];
    const float* b_ih_f   = (const float*)d_in[5];
    const float* b_hh_f   = (const float*)d_in[6];
    const float* w_ih_b   = (const float*)d_in[7];
    const float* w_hh_b   = (const float*)d_in[8];
    const float* b_ih_b   = (const float*)d_in[9];
    const float* b_hh_b   = (const float*)d_in[10];
    const float* h0       = (const float*)d_in[11];
    const float* c0       = (const float*)d_in[12];
    const float* W_tag    = (const float*)d_in[13];
    const float* b_tag    = (const float*)d_in[14];
    const float* trans    = (const float*)d_in[15];

    init_kernel<<<1, 256>>>(h0);

    dim3 g1((4 * HID) / 64, T_LEN / 64, 2);
    xproj_kernel<<<g1, 256>>>(sentence, embed,
                              w_ih_f, b_ih_f, b_hh_f,
                              w_ih_b, b_ih_b, b_hh_b);

    lstm_kernel<<<128, 256>>>(w_hh_f, w_hh_b, c0);

    feats_kernel<<<T_LEN, 256>>>(W_tag, b_tag);

    crf_kernel<<<1, 128>>>(tags, trans, (float*)d_out);
}

// round 3
// speedup vs baseline: 1.6945x; 1.6945x over previous
#include <cuda_runtime.h>
#include <cuda_bf16.h>
#include <cstdint>
#include <cstddef>

#define T_LEN 4096
#define EMBD  300
#define HID   512
#define KTAG  20
#define START_TAG 18
#define STOP_TAG  19
#define NEGV  (-10000.0f)
#define CHUNK 16
#define NCHUNK (T_LEN / CHUNK)   // 256

// ---------------- scratch (static device globals; no allocation) ----------------
__device__ float              g_xproj[2][T_LEN][4 * HID];  // 64 MB
__device__ float              g_hs[2][T_LEN][HID];         // 16 MB
__device__ float              g_feats[T_LEN][KTAG];
__device__ unsigned long long g_hpair[2][2][HID];          // [dir][parity][h]: {tag|bits}
__device__ float              g_tree[2][NCHUNK][KTAG][KTAG];

__device__ __forceinline__ unsigned long long packhf(unsigned tag, float v) {
    return ((unsigned long long)tag << 32) | (unsigned long long)__float_as_uint(v);
}

// fast tanh via exp2-based expf; exact saturation at +-inf of expf
__device__ __forceinline__ float tanh_fast(float x) {
    return 1.f - 2.f / (__expf(2.f * x) + 1.f);
}
__device__ __forceinline__ float sigm_fast(float x) {
    return 1.f / (1.f + __expf(-x));
}

// ---------------- init: seed h0 pairs (tag 0), poison other parity ----------------
__global__ void init_kernel(const float* __restrict__ h0) {
    int tid = threadIdx.x;                // 1024 threads
    int dir = tid >> 9, i = tid & 511;
    g_hpair[dir][0][i] = packhf(0u, h0[dir * HID + i]);
    g_hpair[dir][1][i] = packhf(0x7fffffffu, 0.f);
}

// ---------------- K1: x_proj = emb(gather) @ w_ih^T + b_ih + b_hh ----------------
__global__ __launch_bounds__(256) void xproj_kernel(
    const int*   __restrict__ sentence,
    const float* __restrict__ embed,
    const float* __restrict__ w_ih_f, const float* __restrict__ b_ih_f, const float* __restrict__ b_hh_f,
    const float* __restrict__ w_ih_b, const float* __restrict__ b_ih_b, const float* __restrict__ b_hh_b)
{
    const int dir = blockIdx.z;
    const float* __restrict__ w_ih = dir ? w_ih_b : w_ih_f;
    const float* __restrict__ bi   = dir ? b_ih_b : b_ih_f;
    const float* __restrict__ bh   = dir ? b_hh_b : b_hh_f;

    const int j0 = blockIdx.x * 64;
    const int t0 = blockIdx.y * 64;

    __shared__ __align__(16) float As[8][64];
    __shared__ __align__(16) float Bs[8][64];
    __shared__ int sidx[64];

    const int tid = threadIdx.x;
    if (tid < 64) {
        int t = t0 + tid;
        sidx[tid] = sentence[dir ? (T_LEN - 1 - t) : t];
    }
    __syncthreads();

    const int tx = tid & 15, ty = tid >> 4;
    const int lr = tid >> 2;
    const int le = (tid & 3) * 2;

    float acc[4][4] = {};

    for (int e0 = 0; e0 < EMBD; e0 += 8) {
        const float* arow = embed + (size_t)sidx[lr] * EMBD;
        const float* brow = w_ih + (size_t)(j0 + lr) * EMBD;
        int e = e0 + le;
        As[le][lr]     = (e     < EMBD) ? arow[e]     : 0.f;
        As[le + 1][lr] = (e + 1 < EMBD) ? arow[e + 1] : 0.f;
        Bs[le][lr]     = (e     < EMBD) ? brow[e]     : 0.f;
        Bs[le + 1][lr] = (e + 1 < EMBD) ? brow[e + 1] : 0.f;
        __syncthreads();
#pragma unroll
        for (int kk = 0; kk < 8; kk++) {
            float4 a = *(const float4*)&As[kk][ty * 4];
            float4 b = *(const float4*)&Bs[kk][tx * 4];
            float av[4] = {a.x, a.y, a.z, a.w};
            float bv[4] = {b.x, b.y, b.z, b.w};
#pragma unroll
            for (int i = 0; i < 4; i++)
#pragma unroll
                for (int j = 0; j < 4; j++)
                    acc[i][j] = fmaf(av[i], bv[j], acc[i][j]);
        }
        __syncthreads();
    }

#pragma unroll
    for (int i = 0; i < 4; i++) {
        int t = t0 + ty * 4 + i;
#pragma unroll
        for (int j = 0; j < 4; j++) {
            int jj = j0 + tx * 4 + j;
            g_xproj[dir][t][jj] = acc[i][j] + bi[jj] + bh[jj];
        }
    }
}

// ---------------- K3: persistent BiLSTM, flag-in-data sync ----------------
// 128 CTAs (64/dir). Warp w of a CTA owns h-index hidx=cid*8+w (all 4 gates).
// Lane = gate*8+kg: accumulates row gate*512+hidx over k in [kg*64,kg*64+64).
__global__ __launch_bounds__(256) void lstm_kernel(
    const float* __restrict__ w_hh_f,
    const float* __restrict__ w_hh_b,
    const float* __restrict__ c0)
{
    const int dir = blockIdx.x >> 6;
    const int cid = blockIdx.x & 63;
    const float* __restrict__ w_hh = dir ? w_hh_b : w_hh_f;

    const int tid  = threadIdx.x;
    const int wid  = tid >> 5;
    const int lane = tid & 31;
    const int gate = lane >> 3;
    const int kg   = lane & 7;
    const int hidx = cid * 8 + wid;
    const int row  = gate * HID + hidx;

    // weights, swizzled so smem reads rotate by kg (conflict-free)
    float4 w4[16];
    {
        const float4* wr4 = (const float4*)(w_hh + (size_t)row * HID + kg * 64);
#pragma unroll
        for (int kk = 0; kk < 16; kk++) w4[kk] = wr4[(kk + kg) & 15];
    }

    __shared__ __align__(16) float h_sh[2][HID];

    float creg = (lane == 0) ? c0[dir * HID + hidx] : 0.f;
    float xp   = (kg == 0) ? g_xproj[dir][0][row] : 0.f;

    const unsigned long long* rd0 = g_hpair[dir][0];
    const unsigned long long* rd1 = g_hpair[dir][1];

    for (int t = 0; t < T_LEN; t++) {
        // --- poll own 2 pairs of h_state(t), stash to smem ---
        {
            const unsigned long long* p = ((t & 1) ? rd1 : rd0) + 2 * tid;
            unsigned wanted = (unsigned)t;
            unsigned long long a, b;
            do {
                asm volatile("ld.relaxed.gpu.global.v2.u64 {%0,%1}, [%2];"
                             : "=l"(a), "=l"(b) : "l"(p) : "memory");
            } while ((unsigned)(a >> 32) != wanted || (unsigned)(b >> 32) != wanted);
            h_sh[t & 1][2 * tid]     = __uint_as_float((unsigned)a);
            h_sh[t & 1][2 * tid + 1] = __uint_as_float((unsigned)b);
        }
        __syncthreads();

        // --- matvec: 64-wide chunk per lane, rotated reads ---
        float a0 = (kg == 0) ? xp : 0.f, a1 = 0.f;
        const float* hb = h_sh[t & 1] + kg * 64;
#pragma unroll
        for (int kk = 0; kk < 16; kk++) {
            float4 h4 = *(const float4*)(hb + (((kk + kg) & 15) << 2));
            a0 = fmaf(w4[kk].x, h4.x, a0);
            a1 = fmaf(w4[kk].y, h4.y, a1);
            a0 = fmaf(w4[kk].z, h4.z, a0);
            a1 = fmaf(w4[kk].w, h4.w, a1);
        }
        float acc = a0 + a1;
        // reduce over kg (8 lanes/gate group)
        acc += __shfl_xor_sync(0xffffffffu, acc, 4);
        acc += __shfl_xor_sync(0xffffffffu, acc, 2);
        acc += __shfl_xor_sync(0xffffffffu, acc, 1);
        // gate sums now replicated in each 8-lane group; gather to lane 0
        float vf = __shfl_sync(0xffffffffu, acc, 8);
        float vg = __shfl_sync(0xffffffffu, acc, 16);
        float vo = __shfl_sync(0xffffffffu, acc, 24);
        if (lane == 0) {
            float fi = sigm_fast(acc);       // lane0 holds gate 0 (i)
            float ff = sigm_fast(vf);
            float fo = sigm_fast(vo);
            creg = ff * creg + fi * tanh_fast(vg);
            float hn = fo * tanh_fast(creg);
            unsigned long long* wp =
                (unsigned long long*)(((t + 1) & 1) ? rd1 : rd0) + hidx;
            unsigned long long pv = packhf((unsigned)(t + 1), hn);
            asm volatile("st.relaxed.gpu.global.u64 [%0], %1;" :: "l"(wp), "l"(pv) : "memory");
            g_hs[dir][t][hidx] = hn;
        }
        if (kg == 0 && t + 1 < T_LEN) xp = g_xproj[dir][t + 1][row];
        // no trailing barrier: next poll writes the OTHER h_sh buffer,
        // and the step-start barrier orders reuse two steps later.
    }
}

// ---------------- K4: feats[t,k] = [h_f(t), h_b(t)] . W_tag[k] + b_tag[k] ----------------
__global__ __launch_bounds__(256) void feats_kernel(
    const float* __restrict__ W_tag, const float* __restrict__ b_tag)
{
    const int t = blockIdx.x;
    __shared__ float hsm[2 * HID];
    const int tid = threadIdx.x;
    for (int i = tid; i < HID; i += 256) {
        hsm[i]       = g_hs[0][t][i];
        hsm[HID + i] = g_hs[1][T_LEN - 1 - t][i];
    }
    __syncthreads();
    const int wid = tid >> 5, lane = tid & 31;
    for (int k = wid; k < KTAG; k += 8) {
        const float* wrow = W_tag + (size_t)k * (2 * HID);
        float s = 0.f;
#pragma unroll
        for (int m = 0; m < 32; m++)
            s = fmaf(wrow[m * 32 + lane], hsm[m * 32 + lane], s);
#pragma unroll
        for (int off = 16; off; off >>= 1)
            s += __shfl_xor_sync(0xffffffffu, s, off);
        if (lane == 0) g_feats[t][k] = s + b_tag[k];
    }
}

// ---------------- K5a: per-chunk sequential composition (256 warps) ----------------
// A_t[j][i] = trans[j][i] + feat_t[j];  step: N[j][i] = f[j] + LSE_k(trans[j][k] + M[k][i])
__global__ __launch_bounds__(32) void crf_chunk_kernel(const float* __restrict__ trans)
{
    const int c = blockIdx.x;
    const int lane = threadIdx.x;
    __shared__ float Tsm[KTAG][KTAG];
    __shared__ float Mbuf[2][KTAG][KTAG];
    __shared__ float fsm[KTAG];

    for (int i = lane; i < KTAG * KTAG; i += 32)
        Tsm[i / KTAG][i % KTAG] = trans[i];
    __syncwarp();

    // M = A_{16c}
    if (lane < KTAG) fsm[lane] = g_feats[c * CHUNK][lane];
    __syncwarp();
    for (int e = lane; e < KTAG * KTAG; e += 32)
        Mbuf[0][e / KTAG][e % KTAG] = Tsm[e / KTAG][e % KTAG] + fsm[e / KTAG];
    __syncwarp();

    int cur = 0;
    for (int s = 1; s < CHUNK; s++) {
        if (lane < KTAG) fsm[lane] = g_feats[c * CHUNK + s][lane];
        __syncwarp();
        for (int e = lane; e < KTAG * KTAG; e += 32) {
            int j = e / KTAG, i = e % KTAG;
            float v[KTAG], mx = -3.4e38f;
#pragma unroll
            for (int k = 0; k < KTAG; k++) {
                v[k] = Tsm[j][k] + Mbuf[cur][k][i];
                mx = fmaxf(mx, v[k]);
            }
            float sm = 0.f;
#pragma unroll
            for (int k = 0; k < KTAG; k++) sm += __expf(v[k] - mx);
            Mbuf[cur ^ 1][j][i] = fsm[j] + mx + __logf(sm);
        }
        __syncwarp();
        cur ^= 1;
    }
    for (int e = lane; e < KTAG * KTAG; e += 32)
        g_tree[0][c][e / KTAG][e % KTAG] = Mbuf[cur][e / KTAG][e % KTAG];
}

// ---------------- K5b: tree combine. out[b] = in[2b+1] (.) in[2b] ----------------
__global__ __launch_bounds__(32) void crf_combine_kernel(int s)
{
    const int b = blockIdx.x;
    const int lane = threadIdx.x;
    const float (*in)[KTAG][KTAG]  = g_tree[s & 1];
    float (*out)[KTAG][KTAG]       = g_tree[(s & 1) ^ 1];
    __shared__ float Lo[KTAG][KTAG], Hi[KTAG][KTAG];
    for (int i = lane; i < KTAG * KTAG; i += 32) {
        Lo[i / KTAG][i % KTAG] = in[2 * b][i / KTAG][i % KTAG];
        Hi[i / KTAG][i % KTAG] = in[2 * b + 1][i / KTAG][i % KTAG];
    }
    __syncwarp();
    for (int e = lane; e < KTAG * KTAG; e += 32) {
        int j = e / KTAG, i = e % KTAG;
        float v[KTAG], mx = -3.4e38f;
#pragma unroll
        for (int k = 0; k < KTAG; k++) {
            v[k] = Hi[j][k] + Lo[k][i];
            mx = fmaxf(mx, v[k]);
        }
        float sm = 0.f;
#pragma unroll
        for (int k = 0; k < KTAG; k++) sm += __expf(v[k] - mx);
        out[b][j][i] = mx + __logf(sm);
    }
}

// ---------------- K5c: final score = forward - gold ----------------
__global__ void crf_final_kernel(const int* __restrict__ tags,
                                 const float* __restrict__ trans,
                                 float* __restrict__ out)
{
    __shared__ float partial[128];
    const int tid = threadIdx.x;

    float loc = 0.f;
    for (int t = tid; t < T_LEN; t += 128) {
        int tg = tags[t];
        int pv = t ? tags[t - 1] : START_TAG;
        loc += trans[tg * KTAG + pv] + g_feats[t][tg];
    }
    partial[tid] = loc;
    __syncthreads();

    if (tid == 0) {
        float gold = trans[STOP_TAG * KTAG + tags[T_LEN - 1]];
        for (int i = 0; i < 128; i++) gold += partial[i];

        // alpha = C (.) init ; C = g_tree[0][0] (after 8 combine levels)
        const float (*C)[KTAG] = g_tree[0][0];
        float alpha[KTAG];
        for (int j = 0; j < KTAG; j++) {
            float mx = -3.4e38f, v[KTAG];
            for (int i = 0; i < KTAG; i++) {
                v[i] = C[j][i] + ((i == START_TAG) ? 0.f : NEGV);
                mx = fmaxf(mx, v[i]);
            }
            float sm = 0.f;
            for (int i = 0; i < KTAG; i++) sm += __expf(v[i] - mx);
            alpha[j] = mx + __logf(sm);
        }
        float mx = -3.4e38f;
        for (int j = 0; j < KTAG; j++)
            mx = fmaxf(mx, alpha[j] + trans[STOP_TAG * KTAG + j]);
        float sm = 0.f;
        for (int j = 0; j < KTAG; j++)
            sm += __expf(alpha[j] + trans[STOP_TAG * KTAG + j] - mx);
        out[0] = (mx + __logf(sm)) - gold;
    }
}

// ---------------- launch ----------------
extern "C" void kernel_launch(void* const* d_in, const int* in_sizes, int n_in,
                              void* d_out, int out_size)
{
    const int*   sentence = (const int*)d_in[0];
    const int*   tags     = (const int*)d_in[1];
    const float* embed    = (const float*)d_in[2];
    const float* w_ih_f   = (const float*)d_in[3];
    const float* w_hh_f   = (const float*)d_in[4];
    const float* b_ih_f   = (const float*)d_in[5];
    const float* b_hh_f   = (const float*)d_in[6];
    const float* w_ih_b   = (const float*)d_in[7];
    const float* w_hh_b   = (const float*)d_in[8];
    const float* b_ih_b   = (const float*)d_in[9];
    const float* b_hh_b   = (const float*)d_in[10];
    const float* h0       = (const float*)d_in[11];
    const float* c0       = (const float*)d_in[12];
    const float* W_tag    = (const float*)d_in[13];
    const float* b_tag    = (const float*)d_in[14];
    const float* trans    = (const float*)d_in[15];

    init_kernel<<<1, 1024>>>(h0);

    dim3 g1((4 * HID) / 64, T_LEN / 64, 2);
    xproj_kernel<<<g1, 256>>>(sentence, embed,
                              w_ih_f, b_ih_f, b_hh_f,
                              w_ih_b, b_ih_b, b_hh_b);

    lstm_kernel<<<128, 256>>>(w_hh_f, w_hh_b, c0);

    feats_kernel<<<T_LEN, 256>>>(W_tag, b_tag);

    crf_chunk_kernel<<<NCHUNK, 32>>>(trans);
    for (int s = 0; s < 8; s++)
        crf_combine_kernel<<<(NCHUNK / 2) >> s, 32>>>(s);
    crf_final_kernel<<<1, 128>>>(tags, trans, (float*)d_out);
}